// round 3
// baseline (speedup 1.0000x reference)
#include <cuda_runtime.h>
#include <math.h>

#define NCTA 128
#define NTHR 256
#define Bb 256      // batch
#define Ss 512      // seq len
#define Ii 256      // input dim
#define Hh 512      // hidden dim
#define BBd 256     // backbone dim
#define Oo 128      // out dim

// shared memory layout (in floats)
#define P1   772    // pitch for stage1 weight rows (K=768 + pad)
#define PB   260    // pitch for backbone/head weight rows (K=256 + pad)
#define PA1  132    // act pitch, 32-row chunks (KC=128 + pad)
#define PAH  68     // act pitch, 64-row chunks (KC=64 + pad)

#define OFF_W1  0
#define SZ_W1   (16 * P1)          // 12352
#define OFF_WB  (OFF_W1 + SZ_W1)
#define SZ_WB   (48 * PB)          // 12480
#define OFF_WH  (OFF_WB + SZ_WB)
#define SZ_WH   (64 * PB)          // 16640
#define OFF_ACT (OFF_WH + SZ_WH)
#define SZ_ACTBUF 4352             // max(32*132, 64*68)
#define SZ_ACT  (2 * SZ_ACTBUF)
#define SMEM_FLOATS (OFF_ACT + SZ_ACT)   // 50176 floats
#define SMEM_BYTES  (SMEM_FLOATS * 4)    // 200704 B

// ---------------- device scratch (static globals: allocation-free) ----------
__device__ float g_h[Bb * Hh];       // hidden state  [256][512]
__device__ float g_zA[Bb * BBd];     // backbone ping  [256][256]
__device__ float g_zB[Bb * BBd];     // backbone pong  [256][256]
__device__ unsigned g_barCount = 0;
__device__ unsigned g_barGen   = 0;
__device__ int      g_abort    = 0;  // watchdog flag: residency-failure diagnostic

// ---------------- grid barrier with watchdog -------------------------------
// All 128 CTAs are expected co-resident (200KB smem -> 1 CTA/SM, 128 <= 148 SMs).
// If that assumption is ever violated, the watchdog converts a deadlock into a
// fast (wrong-answer) termination so the harness can report it.
__device__ __forceinline__ void grid_barrier() {
    __syncthreads();
    if (threadIdx.x == 0) {
        if (!*(volatile int*)&g_abort) {
            __threadfence();
            volatile unsigned* vgen = (volatile unsigned*)&g_barGen;
            unsigned gen = *vgen;                 // read BEFORE arriving (safe)
            atomicAdd(&g_barCount, 1);
            // re-check: use fetch-back of count to detect last arrival
            if (atomicAdd(&g_barCount, 0) == 0) {} // (no-op; last-arrival below)
            // standard last-arrival detection via returned rank:
            // (we recompute: the first atomicAdd returned the rank)
            // -- restructured below --
            (void)0;
            // NOTE: rank captured in the add above is needed; fall through to
            // spin/release logic implemented with the captured value.
            // (see full implementation in grid_barrier_impl)
        }
    }
    __syncthreads();
}

// Full implementation (used instead of the stub above).
__device__ __forceinline__ void grid_barrier_impl() {
    __syncthreads();
    if (threadIdx.x == 0) {
        if (!*(volatile int*)&g_abort) {
            __threadfence();
            volatile unsigned* vgen = (volatile unsigned*)&g_barGen;
            unsigned gen = *vgen;                 // read BEFORE arriving (safe)
            unsigned rank = atomicAdd(&g_barCount, 1);
            if (rank == NCTA - 1) {
                atomicExch(&g_barCount, 0);
                __threadfence();
                atomicAdd(&g_barGen, 1);
            } else {
                long long t0 = clock64();
                while (*vgen == gen) {
                    __nanosleep(32);
                    if (*(volatile int*)&g_abort) break;
                    if (clock64() - t0 > 2000000000LL) {   // ~1s: residency failure
                        atomicExch(&g_abort, 1);
                        break;
                    }
                }
            }
            __threadfence();
        }
    }
    __syncthreads();
}

// ---------------- cp.async helpers ----------------------------------------
__device__ __forceinline__ void cp16(float* sdst, const float* gsrc) {
    unsigned saddr = (unsigned)__cvta_generic_to_shared(sdst);
    asm volatile("cp.async.cg.shared.global [%0], [%1], 16;" :: "r"(saddr), "l"(gsrc));
}
__device__ __forceinline__ void cp_commit() { asm volatile("cp.async.commit_group;"); }
__device__ __forceinline__ void cp_wait0()  { asm volatile("cp.async.wait_group 0;"); }
__device__ __forceinline__ void cp_wait1()  { asm volatile("cp.async.wait_group 1;"); }

// load 32 rows x 128 floats into sdst (pitch PA1), gbase = row0 of chunk
__device__ __forceinline__ void load_rows32(float* sdst, const float* gbase, int gstride) {
    int tid = threadIdx.x;
#pragma unroll
    for (int i = 0; i < 4; i++) {
        int e = tid + i * 256;
        int r = e >> 5, v = e & 31;
        cp16(sdst + r * PA1 + v * 4, gbase + (size_t)r * gstride + v * 4);
    }
}
// load 64 rows x 64 floats into sdst (pitch PAH)
__device__ __forceinline__ void load_rows64(float* sdst, const float* gbase, int gstride) {
    int tid = threadIdx.x;
#pragma unroll
    for (int i = 0; i < 4; i++) {
        int e = tid + i * 256;
        int r = e >> 4, v = e & 15;
        cp16(sdst + r * PAH + v * 4, gbase + (size_t)r * gstride + v * 4);
    }
}

// 32x16 output tile: accumulate one staged chunk of 128 k's
__device__ __forceinline__ void mac32x16(const float* sA, const float* wrow,
                                         float& acc0, float& acc1, int mg) {
    const float4* a0 = (const float4*)(sA + (mg * 2) * PA1);
    const float4* a1 = (const float4*)(sA + (mg * 2 + 1) * PA1);
    const float4* w4 = (const float4*)wrow;
#pragma unroll
    for (int q = 0; q < 32; q++) {
        float4 w = w4[q];
        float4 x0 = a0[q];
        float4 x1 = a1[q];
        acc0 += x0.x * w.x + x0.y * w.y + x0.z * w.z + x0.w * w.w;
        acc1 += x1.x * w.x + x1.y * w.y + x1.z * w.z + x1.w * w.w;
    }
}

// heads tile: 64 rows x (16 cols x 4 heads); accumulate one chunk of 64 k's
__device__ __forceinline__ void mac_heads(const float* sA, const float* wbase,
                                          int mg, int ng, float acc[4][4]) {
    const float4* a0 = (const float4*)(sA + (mg * 4 + 0) * PAH);
    const float4* a1 = (const float4*)(sA + (mg * 4 + 1) * PAH);
    const float4* a2 = (const float4*)(sA + (mg * 4 + 2) * PAH);
    const float4* a3 = (const float4*)(sA + (mg * 4 + 3) * PAH);
    const float4* w0 = (const float4*)(wbase + (0 * 16 + ng) * PB);
    const float4* w1 = (const float4*)(wbase + (1 * 16 + ng) * PB);
    const float4* w2 = (const float4*)(wbase + (2 * 16 + ng) * PB);
    const float4* w3 = (const float4*)(wbase + (3 * 16 + ng) * PB);
#pragma unroll
    for (int q = 0; q < 16; q++) {
        float4 wv0 = w0[q], wv1 = w1[q], wv2 = w2[q], wv3 = w3[q];
        float4 av;
        av = a0[q];
        acc[0][0] += av.x * wv0.x + av.y * wv0.y + av.z * wv0.z + av.w * wv0.w;
        acc[0][1] += av.x * wv1.x + av.y * wv1.y + av.z * wv1.z + av.w * wv1.w;
        acc[0][2] += av.x * wv2.x + av.y * wv2.y + av.z * wv2.z + av.w * wv2.w;
        acc[0][3] += av.x * wv3.x + av.y * wv3.y + av.z * wv3.z + av.w * wv3.w;
        av = a1[q];
        acc[1][0] += av.x * wv0.x + av.y * wv0.y + av.z * wv0.z + av.w * wv0.w;
        acc[1][1] += av.x * wv1.x + av.y * wv1.y + av.z * wv1.z + av.w * wv1.w;
        acc[1][2] += av.x * wv2.x + av.y * wv2.y + av.z * wv2.z + av.w * wv2.w;
        acc[1][3] += av.x * wv3.x + av.y * wv3.y + av.z * wv3.z + av.w * wv3.w;
        av = a2[q];
        acc[2][0] += av.x * wv0.x + av.y * wv0.y + av.z * wv0.z + av.w * wv0.w;
        acc[2][1] += av.x * wv1.x + av.y * wv1.y + av.z * wv1.z + av.w * wv1.w;
        acc[2][2] += av.x * wv2.x + av.y * wv2.y + av.z * wv2.z + av.w * wv2.w;
        acc[2][3] += av.x * wv3.x + av.y * wv3.y + av.z * wv3.z + av.w * wv3.w;
        av = a3[q];
        acc[3][0] += av.x * wv0.x + av.y * wv0.y + av.z * wv0.z + av.w * wv0.w;
        acc[3][1] += av.x * wv1.x + av.y * wv1.y + av.z * wv1.z + av.w * wv1.w;
        acc[3][2] += av.x * wv2.x + av.y * wv2.y + av.z * wv2.z + av.w * wv2.w;
        acc[3][3] += av.x * wv3.x + av.y * wv3.y + av.z * wv3.z + av.w * wv3.w;
    }
}

__global__ void __launch_bounds__(NTHR, 1)
lnn_kernel(const float* __restrict__ x,     const float* __restrict__ ts,
           const float* __restrict__ Wb0,   const float* __restrict__ bb0,
           const float* __restrict__ Wbs,   const float* __restrict__ bbs,
           const float* __restrict__ W_ff1, const float* __restrict__ b_ff1,
           const float* __restrict__ W_ff2, const float* __restrict__ b_ff2,
           const float* __restrict__ W_ta,  const float* __restrict__ b_ta,
           const float* __restrict__ W_tb,  const float* __restrict__ b_tb,
           const float* __restrict__ W_out, const float* __restrict__ b_out,
           float* __restrict__ out) {
    extern __shared__ float smf[];
    const int tid = threadIdx.x;
    const int g   = blockIdx.x;
    const int n   = tid & 15;     // column within 16-wide N slice (also ng)
    const int mg  = tid >> 4;     // 0..15
    const int m1  = g >> 4;       // stage1/backbone: 8 M-tiles of 32
    const int n1  = g & 15;       // 16 N-slices of 16
    const int mh  = g >> 5;       // heads: 4 M-tiles of 64
    const int jh  = g & 31;       // heads: 32 j-slices of 16

    // reset watchdog (all CTAs write same value; benign race)
    if (tid == 0) *(volatile int*)&g_abort = 0;

    // ---- one-time: weight slices into SMEM (transposed, k contiguous) ----
    for (int e = tid; e < 16 * 768; e += NTHR) {
        int nn = e / 768, k = e % 768;
        smf[OFF_W1 + nn * P1 + k] = Wb0[k * BBd + n1 * 16 + nn];
    }
    for (int e = tid; e < 3 * 16 * 256; e += NTHR) {
        int l = e / (16 * 256);
        int r = e % (16 * 256);
        int nn = r / 256, k = r % 256;
        smf[OFF_WB + (l * 16 + nn) * PB + k] = Wbs[(l * BBd + k) * BBd + n1 * 16 + nn];
    }
    for (int e = tid; e < 64 * 256; e += NTHR) {
        int r = e / 256, k = e % 256;
        int hh = r / 16, ng = r % 16;
        const float* Wsrc = (hh == 0) ? W_ff1 : (hh == 1) ? W_ff2 : (hh == 2) ? W_ta : W_tb;
        smf[OFF_WH + r * PB + k] = Wsrc[k * Hh + jh * 16 + ng];
    }
    // biases into registers (fixed per thread)
    float bz0   = bb0[n1 * 16 + n];
    float bb_l0 = bbs[0 * BBd + n1 * 16 + n];
    float bb_l1 = bbs[1 * BBd + n1 * 16 + n];
    float bb_l2 = bbs[2 * BBd + n1 * 16 + n];
    float bf1   = b_ff1[jh * 16 + n];
    float bf2   = b_ff2[jh * 16 + n];
    float bta   = b_ta [jh * 16 + n];
    float btb   = b_tb [jh * 16 + n];

    // zero hidden state (re-done every replay -> deterministic)
    for (int e = tid; e < 1024; e += NTHR) g_h[g * 1024 + e] = 0.0f;
    __syncthreads();
    grid_barrier_impl();

    float* act0 = smf + OFF_ACT;
    float* act1 = smf + OFF_ACT + SZ_ACTBUF;

    for (int t = 0; t < Ss; t++) {
        if (*(volatile int*)&g_abort) break;   // watchdog fired: terminate fast
        // ================= stage 1: z0 = tanh([x_t,h] @ Wb0 + bb0) ========
        {
            float acc0 = 0.f, acc1 = 0.f;
            // chunk sources: c in [0,1] -> x, c in [2,5] -> h
            load_rows32(act0, x + ((size_t)(m1 * 32) * Ss + t) * Ii + 0 * 128, Ss * Ii);
            cp_commit();
#pragma unroll
            for (int c = 0; c < 6; c++) {
                float* cur = (c & 1) ? act1 : act0;
                if (c < 5) {
                    int cn = c + 1;
                    float* nxt = (cn & 1) ? act1 : act0;
                    if (cn < 2)
                        load_rows32(nxt, x + ((size_t)(m1 * 32) * Ss + t) * Ii + cn * 128, Ss * Ii);
                    else
                        load_rows32(nxt, g_h + (m1 * 32) * Hh + (cn - 2) * 128, Hh);
                    cp_commit();
                    cp_wait1();
                } else {
                    cp_wait0();
                }
                __syncthreads();
                mac32x16(cur, smf + OFF_W1 + n * P1 + c * 128, acc0, acc1, mg);
                __syncthreads();
            }
            int j = n1 * 16 + n;
            g_zA[(m1 * 32 + mg * 2) * BBd + j]     = tanhf(acc0 + bz0);
            g_zA[(m1 * 32 + mg * 2 + 1) * BBd + j] = tanhf(acc1 + bz0);
        }
        grid_barrier_impl();

        // ================= backbone: 3x z = tanh(z @ Wbs[l] + bbs[l]) =====
#pragma unroll
        for (int l = 0; l < 3; l++) {
            const float* zin = (l == 1) ? g_zB : g_zA;
            float*       zot = (l == 1) ? g_zA : g_zB;
            float acc0 = 0.f, acc1 = 0.f;
            load_rows32(act0, zin + (m1 * 32) * BBd + 0, BBd);
            cp_commit();
#pragma unroll
            for (int c = 0; c < 2; c++) {
                if (c == 0) {
                    load_rows32(act1, zin + (m1 * 32) * BBd + 128, BBd);
                    cp_commit();
                    cp_wait1();
                } else {
                    cp_wait0();
                }
                __syncthreads();
                mac32x16((c ? act1 : act0), smf + OFF_WB + (l * 16 + n) * PB + c * 128,
                         acc0, acc1, mg);
                __syncthreads();
            }
            int j = n1 * 16 + n;
            float bl = (l == 0) ? bb_l0 : (l == 1) ? bb_l1 : bb_l2;
            zot[(m1 * 32 + mg * 2) * BBd + j]     = tanhf(acc0 + bl);
            zot[(m1 * 32 + mg * 2 + 1) * BBd + j] = tanhf(acc1 + bl);
            grid_barrier_impl();
        }

        // ================= heads: ff1/ff2/ta/tb + gate -> new h ===========
        {
            float acc[4][4];
#pragma unroll
            for (int i = 0; i < 4; i++)
#pragma unroll
                for (int hh = 0; hh < 4; hh++) acc[i][hh] = 0.f;

            load_rows64(act0, g_zB + (mh * 64) * BBd + 0, BBd);
            cp_commit();
#pragma unroll
            for (int c = 0; c < 4; c++) {
                float* cur = (c & 1) ? act1 : act0;
                if (c < 3) {
                    float* nxt = ((c + 1) & 1) ? act1 : act0;
                    load_rows64(nxt, g_zB + (mh * 64) * BBd + (c + 1) * 64, BBd);
                    cp_commit();
                    cp_wait1();
                } else {
                    cp_wait0();
                }
                __syncthreads();
                mac_heads(cur, smf + OFF_WH + c * 64, mg, n, acc);
                __syncthreads();
            }
            int j = jh * 16 + n;
#pragma unroll
            for (int i = 0; i < 4; i++) {
                int b = mh * 64 + mg * 4 + i;
                float tst = ts[(size_t)b * Ss + t];
                float f1  = tanhf(acc[i][0] + bf1);
                float f2  = tanhf(acc[i][1] + bf2);
                float ta_ = acc[i][2] + bta;
                float tb_ = acc[i][3] + btb;
                float ti  = 1.0f / (1.0f + expf(-(ta_ * tst + tb_)));
                g_h[b * Hh + j] = f1 + ti * (f2 - f1);
            }
        }
        grid_barrier_impl();
    }

    // ================= final: out = h_last @ W_out + b_out ================
    {
        int mo = g >> 2, no = g & 3;
        int m  = mo * 8 + (tid >> 5);
        int nn = no * 32 + (tid & 31);
        float acc = b_out[nn];
        const float* hr = g_h + m * Hh;
#pragma unroll 8
        for (int k = 0; k < Hh; k++) acc += hr[k] * W_out[k * Oo + nn];
        out[m * Oo + nn] = acc;
    }
}

extern "C" void kernel_launch(void* const* d_in, const int* in_sizes, int n_in,
                              void* d_out, int out_size) {
    const float* x     = (const float*)d_in[0];
    const float* ts    = (const float*)d_in[1];
    const float* Wb0   = (const float*)d_in[2];
    const float* bb0   = (const float*)d_in[3];
    const float* Wbs   = (const float*)d_in[4];
    const float* bbs   = (const float*)d_in[5];
    const float* W_ff1 = (const float*)d_in[6];
    const float* b_ff1 = (const float*)d_in[7];
    const float* W_ff2 = (const float*)d_in[8];
    const float* b_ff2 = (const float*)d_in[9];
    const float* W_ta  = (const float*)d_in[10];
    const float* b_ta  = (const float*)d_in[11];
    const float* W_tb  = (const float*)d_in[12];
    const float* b_tb  = (const float*)d_in[13];
    const float* W_out = (const float*)d_in[14];
    const float* b_out = (const float*)d_in[15];

    cudaFuncSetAttribute(lnn_kernel, cudaFuncAttributeMaxDynamicSharedMemorySize, SMEM_BYTES);
    lnn_kernel<<<NCTA, NTHR, SMEM_BYTES>>>(x, ts, Wb0, bb0, Wbs, bbs,
                                           W_ff1, b_ff1, W_ff2, b_ff2,
                                           W_ta, b_ta, W_tb, b_tb,
                                           W_out, b_out, (float*)d_out);
}

// round 4
// speedup vs baseline: 1.3227x; 1.3227x over previous
#include <cuda_runtime.h>
#include <math.h>

#define NCTA 128
#define NTHR 256
#define Bb 256      // batch
#define Ss 512      // seq len
#define Ii 256      // input dim
#define Hh 512      // hidden dim
#define BBd 256     // backbone dim
#define Oo 128      // out dim

// shared memory layout (in floats)
#define P1   772    // pitch for stage1 weight rows (K=768 + pad)
#define PB   260    // pitch for backbone/head weight rows (K=256 + pad)
#define PA1  132    // act pitch, 32-row chunks (KC=128 + pad)
#define PAH  68     // act pitch, 64-row chunks (KC=64 + pad)

#define OFF_W1  0
#define SZ_W1   (16 * P1)          // 12352
#define OFF_WB  (OFF_W1 + SZ_W1)
#define SZ_WB   (48 * PB)          // 12480
#define OFF_WH  (OFF_WB + SZ_WB)
#define SZ_WH   (64 * PB)          // 16640
#define OFF_ACT (OFF_WH + SZ_WH)
#define SZ_ACTBUF 4352             // max(32*132, 64*68)
#define SZ_ACT  (2 * SZ_ACTBUF)
#define SMEM_FLOATS (OFF_ACT + SZ_ACT)   // 50176 floats
#define SMEM_BYTES  (SMEM_FLOATS * 4)    // 200704 B

typedef unsigned long long u64;

// ---------------- device scratch (static globals: allocation-free) ----------
__device__ float g_h[Bb * Hh];       // hidden state  [256][512]
__device__ float g_zA[Bb * BBd];     // backbone ping  [256][256]
__device__ float g_zB[Bb * BBd];     // backbone pong  [256][256]
__device__ int   g_abort = 0;        // watchdog flag

// group barriers: batch-row groups are fully independent pipelines.
struct __align__(128) Bar { unsigned count; unsigned gen; unsigned pad[30]; };
__device__ Bar g_bar16[8];           // per-m1 groups (16 CTAs each)
__device__ Bar g_bar32[4];           // per-mh groups (32 CTAs each)

// ---------------- group barrier with watchdog ------------------------------
__device__ __forceinline__ void group_barrier(Bar* b, unsigned nctas) {
    __syncthreads();
    if (threadIdx.x == 0) {
        if (!*(volatile int*)&g_abort) {
            __threadfence();
            volatile unsigned* vgen = (volatile unsigned*)&b->gen;
            unsigned gen = *vgen;                 // read BEFORE arriving
            unsigned rank = atomicAdd(&b->count, 1);
            if (rank == nctas - 1) {
                atomicExch(&b->count, 0);
                __threadfence();
                atomicAdd((unsigned*)&b->gen, 1);
            } else {
                long long t0 = clock64();
                while (*vgen == gen) {
                    __nanosleep(32);
                    if (*(volatile int*)&g_abort) break;
                    if (clock64() - t0 > 2000000000LL) {   // ~1s: residency failure
                        atomicExch(&g_abort, 1);
                        break;
                    }
                }
            }
            __threadfence();
        }
    }
    __syncthreads();
}

// ---------------- packed f32x2 FMA helpers ---------------------------------
__device__ __forceinline__ u64 ffma2(u64 a, u64 b, u64 c) {
    u64 d;
    asm("fma.rn.f32x2 %0, %1, %2, %3;" : "=l"(d) : "l"(a), "l"(b), "l"(c));
    return d;
}
__device__ __forceinline__ float sum2(u64 v) {
    union { u64 u; float2 f; } cv; cv.u = v;
    return cv.f.x + cv.f.y;
}

// ---------------- cp.async helpers ----------------------------------------
__device__ __forceinline__ void cp16(float* sdst, const float* gsrc) {
    unsigned saddr = (unsigned)__cvta_generic_to_shared(sdst);
    asm volatile("cp.async.cg.shared.global [%0], [%1], 16;" :: "r"(saddr), "l"(gsrc));
}
__device__ __forceinline__ void cp_commit() { asm volatile("cp.async.commit_group;"); }
__device__ __forceinline__ void cp_wait0()  { asm volatile("cp.async.wait_group 0;"); }
__device__ __forceinline__ void cp_wait1()  { asm volatile("cp.async.wait_group 1;"); }

// load 32 rows x 128 floats into sdst (pitch PA1)
__device__ __forceinline__ void load_rows32(float* sdst, const float* gbase, int gstride) {
    int tid = threadIdx.x;
#pragma unroll
    for (int i = 0; i < 4; i++) {
        int e = tid + i * 256;
        int r = e >> 5, v = e & 31;
        cp16(sdst + r * PA1 + v * 4, gbase + (size_t)r * gstride + v * 4);
    }
}
// load 64 rows x 64 floats into sdst (pitch PAH)
__device__ __forceinline__ void load_rows64(float* sdst, const float* gbase, int gstride) {
    int tid = threadIdx.x;
#pragma unroll
    for (int i = 0; i < 4; i++) {
        int e = tid + i * 256;
        int r = e >> 4, v = e & 15;
        cp16(sdst + r * PAH + v * 4, gbase + (size_t)r * gstride + v * 4);
    }
}

// 32x16 output tile: one staged chunk of 128 k's. 4 independent packed chains.
__device__ __forceinline__ void mac32x16(const float* sA, const float* wrow,
                                         u64& p0a, u64& p0b, u64& p1a, u64& p1b, int mg) {
    const ulonglong2* a0 = (const ulonglong2*)(sA + (mg * 2) * PA1);
    const ulonglong2* a1 = (const ulonglong2*)(sA + (mg * 2 + 1) * PA1);
    const ulonglong2* w4 = (const ulonglong2*)wrow;
#pragma unroll
    for (int q = 0; q < 32; q++) {
        ulonglong2 w  = w4[q];
        ulonglong2 x0 = a0[q];
        ulonglong2 x1 = a1[q];
        p0a = ffma2(x0.x, w.x, p0a);
        p0b = ffma2(x0.y, w.y, p0b);
        p1a = ffma2(x1.x, w.x, p1a);
        p1b = ffma2(x1.y, w.y, p1b);
    }
}

// heads tile: 64 rows x (16 cols x 4 heads); one chunk of 64 k's.
// 16 independent packed accumulator chains.
__device__ __forceinline__ void mac_heads(const float* sA, const float* wbase,
                                          int mg, int ng, u64 acc[4][4]) {
    const ulonglong2* a0 = (const ulonglong2*)(sA + (mg * 4 + 0) * PAH);
    const ulonglong2* a1 = (const ulonglong2*)(sA + (mg * 4 + 1) * PAH);
    const ulonglong2* a2 = (const ulonglong2*)(sA + (mg * 4 + 2) * PAH);
    const ulonglong2* a3 = (const ulonglong2*)(sA + (mg * 4 + 3) * PAH);
    const ulonglong2* w0 = (const ulonglong2*)(wbase + (0 * 16 + ng) * PB);
    const ulonglong2* w1 = (const ulonglong2*)(wbase + (1 * 16 + ng) * PB);
    const ulonglong2* w2 = (const ulonglong2*)(wbase + (2 * 16 + ng) * PB);
    const ulonglong2* w3 = (const ulonglong2*)(wbase + (3 * 16 + ng) * PB);
#pragma unroll
    for (int q = 0; q < 16; q++) {
        ulonglong2 wv0 = w0[q], wv1 = w1[q], wv2 = w2[q], wv3 = w3[q];
        ulonglong2 av;
        av = a0[q];
        acc[0][0] = ffma2(av.x, wv0.x, acc[0][0]); acc[0][0] = ffma2(av.y, wv0.y, acc[0][0]);
        acc[0][1] = ffma2(av.x, wv1.x, acc[0][1]); acc[0][1] = ffma2(av.y, wv1.y, acc[0][1]);
        acc[0][2] = ffma2(av.x, wv2.x, acc[0][2]); acc[0][2] = ffma2(av.y, wv2.y, acc[0][2]);
        acc[0][3] = ffma2(av.x, wv3.x, acc[0][3]); acc[0][3] = ffma2(av.y, wv3.y, acc[0][3]);
        av = a1[q];
        acc[1][0] = ffma2(av.x, wv0.x, acc[1][0]); acc[1][0] = ffma2(av.y, wv0.y, acc[1][0]);
        acc[1][1] = ffma2(av.x, wv1.x, acc[1][1]); acc[1][1] = ffma2(av.y, wv1.y, acc[1][1]);
        acc[1][2] = ffma2(av.x, wv2.x, acc[1][2]); acc[1][2] = ffma2(av.y, wv2.y, acc[1][2]);
        acc[1][3] = ffma2(av.x, wv3.x, acc[1][3]); acc[1][3] = ffma2(av.y, wv3.y, acc[1][3]);
        av = a2[q];
        acc[2][0] = ffma2(av.x, wv0.x, acc[2][0]); acc[2][0] = ffma2(av.y, wv0.y, acc[2][0]);
        acc[2][1] = ffma2(av.x, wv1.x, acc[2][1]); acc[2][1] = ffma2(av.y, wv1.y, acc[2][1]);
        acc[2][2] = ffma2(av.x, wv2.x, acc[2][2]); acc[2][2] = ffma2(av.y, wv2.y, acc[2][2]);
        acc[2][3] = ffma2(av.x, wv3.x, acc[2][3]); acc[2][3] = ffma2(av.y, wv3.y, acc[2][3]);
        av = a3[q];
        acc[3][0] = ffma2(av.x, wv0.x, acc[3][0]); acc[3][0] = ffma2(av.y, wv0.y, acc[3][0]);
        acc[3][1] = ffma2(av.x, wv1.x, acc[3][1]); acc[3][1] = ffma2(av.y, wv1.y, acc[3][1]);
        acc[3][2] = ffma2(av.x, wv2.x, acc[3][2]); acc[3][2] = ffma2(av.y, wv2.y, acc[3][2]);
        acc[3][3] = ffma2(av.x, wv3.x, acc[3][3]); acc[3][3] = ffma2(av.y, wv3.y, acc[3][3]);
    }
}

__global__ void __launch_bounds__(NTHR, 1)
lnn_kernel(const float* __restrict__ x,     const float* __restrict__ ts,
           const float* __restrict__ Wb0,   const float* __restrict__ bb0,
           const float* __restrict__ Wbs,   const float* __restrict__ bbs,
           const float* __restrict__ W_ff1, const float* __restrict__ b_ff1,
           const float* __restrict__ W_ff2, const float* __restrict__ b_ff2,
           const float* __restrict__ W_ta,  const float* __restrict__ b_ta,
           const float* __restrict__ W_tb,  const float* __restrict__ b_tb,
           const float* __restrict__ W_out, const float* __restrict__ b_out,
           float* __restrict__ out) {
    extern __shared__ float smf[];
    const int tid = threadIdx.x;
    const int g   = blockIdx.x;
    const int n   = tid & 15;     // column within 16-wide N slice
    const int mg  = tid >> 4;     // 0..15
    const int m1  = g >> 4;       // stage1/backbone: 8 M-tiles of 32
    const int n1  = g & 15;       // 16 N-slices of 16
    const int mh  = g >> 5;       // heads: 4 M-tiles of 64
    const int jh  = g & 31;       // heads: 32 j-slices of 16

    Bar* barS = &g_bar16[m1];     // stage1/backbone scope: 16 CTAs sharing rows
    Bar* barH = &g_bar32[mh];     // heads scope: 32 CTAs sharing 64 rows

    if (tid == 0) *(volatile int*)&g_abort = 0;   // reset watchdog (benign race)

    // ---- one-time: weight slices into SMEM (transposed, k contiguous) ----
    for (int e = tid; e < 16 * 768; e += NTHR) {
        int nn = e / 768, k = e % 768;
        smf[OFF_W1 + nn * P1 + k] = Wb0[k * BBd + n1 * 16 + nn];
    }
    for (int e = tid; e < 3 * 16 * 256; e += NTHR) {
        int l = e / (16 * 256);
        int r = e % (16 * 256);
        int nn = r / 256, k = r % 256;
        smf[OFF_WB + (l * 16 + nn) * PB + k] = Wbs[(l * BBd + k) * BBd + n1 * 16 + nn];
    }
    for (int e = tid; e < 64 * 256; e += NTHR) {
        int r = e / 256, k = e % 256;
        int hh = r / 16, ng = r % 16;
        const float* Wsrc = (hh == 0) ? W_ff1 : (hh == 1) ? W_ff2 : (hh == 2) ? W_ta : W_tb;
        smf[OFF_WH + r * PB + k] = Wsrc[k * Hh + jh * 16 + ng];
    }
    // biases into registers
    float bz0   = bb0[n1 * 16 + n];
    float bb_l0 = bbs[0 * BBd + n1 * 16 + n];
    float bb_l1 = bbs[1 * BBd + n1 * 16 + n];
    float bb_l2 = bbs[2 * BBd + n1 * 16 + n];
    float bf1   = b_ff1[jh * 16 + n];
    float bf2   = b_ff2[jh * 16 + n];
    float bta   = b_ta [jh * 16 + n];
    float btb   = b_tb [jh * 16 + n];

    // zero hidden state rows owned by this CTA (rows 2g, 2g+1 — group-local)
    for (int e = tid; e < 1024; e += NTHR) g_h[g * 1024 + e] = 0.0f;
    __syncthreads();
    group_barrier(barH, 32);

    float* act0 = smf + OFF_ACT;
    float* act1 = smf + OFF_ACT + SZ_ACTBUF;

    for (int t = 0; t < Ss; t++) {
        if (*(volatile int*)&g_abort) break;
        // ================= stage 1: z0 = tanh([x_t,h] @ Wb0 + bb0) ========
        {
            u64 p0a = 0, p0b = 0, p1a = 0, p1b = 0;
            load_rows32(act0, x + ((size_t)(m1 * 32) * Ss + t) * Ii + 0 * 128, Ss * Ii);
            cp_commit();
#pragma unroll
            for (int c = 0; c < 6; c++) {
                float* cur = (c & 1) ? act1 : act0;
                if (c < 5) {
                    int cn = c + 1;
                    float* nxt = (cn & 1) ? act1 : act0;
                    if (cn < 2)
                        load_rows32(nxt, x + ((size_t)(m1 * 32) * Ss + t) * Ii + cn * 128, Ss * Ii);
                    else
                        load_rows32(nxt, g_h + (m1 * 32) * Hh + (cn - 2) * 128, Hh);
                    cp_commit();
                    cp_wait1();
                } else {
                    cp_wait0();
                }
                __syncthreads();
                mac32x16(cur, smf + OFF_W1 + n * P1 + c * 128, p0a, p0b, p1a, p1b, mg);
                __syncthreads();
            }
            int j = n1 * 16 + n;
            float acc0 = sum2(p0a) + sum2(p0b);
            float acc1 = sum2(p1a) + sum2(p1b);
            g_zA[(m1 * 32 + mg * 2) * BBd + j]     = tanhf(acc0 + bz0);
            g_zA[(m1 * 32 + mg * 2 + 1) * BBd + j] = tanhf(acc1 + bz0);
        }
        group_barrier(barS, 16);

        // ================= backbone: 3x z = tanh(z @ Wbs[l] + bbs[l]) =====
#pragma unroll
        for (int l = 0; l < 3; l++) {
            const float* zin = (l == 1) ? g_zB : g_zA;
            float*       zot = (l == 1) ? g_zA : g_zB;
            u64 p0a = 0, p0b = 0, p1a = 0, p1b = 0;
            load_rows32(act0, zin + (m1 * 32) * BBd + 0, BBd);
            cp_commit();
#pragma unroll
            for (int c = 0; c < 2; c++) {
                if (c == 0) {
                    load_rows32(act1, zin + (m1 * 32) * BBd + 128, BBd);
                    cp_commit();
                    cp_wait1();
                } else {
                    cp_wait0();
                }
                __syncthreads();
                mac32x16((c ? act1 : act0), smf + OFF_WB + (l * 16 + n) * PB + c * 128,
                         p0a, p0b, p1a, p1b, mg);
                __syncthreads();
            }
            int j = n1 * 16 + n;
            float bl = (l == 0) ? bb_l0 : (l == 1) ? bb_l1 : bb_l2;
            float acc0 = sum2(p0a) + sum2(p0b);
            float acc1 = sum2(p1a) + sum2(p1b);
            zot[(m1 * 32 + mg * 2) * BBd + j]     = tanhf(acc0 + bl);
            zot[(m1 * 32 + mg * 2 + 1) * BBd + j] = tanhf(acc1 + bl);
            // last backbone barrier must cover the heads scope (2 m1-tiles)
            if (l < 2) group_barrier(barS, 16);
            else       group_barrier(barH, 32);
        }

        // ================= heads: ff1/ff2/ta/tb + gate -> new h ===========
        {
            u64 acc[4][4];
#pragma unroll
            for (int i = 0; i < 4; i++)
#pragma unroll
                for (int hh = 0; hh < 4; hh++) acc[i][hh] = 0;

            load_rows64(act0, g_zB + (mh * 64) * BBd + 0, BBd);
            cp_commit();
#pragma unroll
            for (int c = 0; c < 4; c++) {
                float* cur = (c & 1) ? act1 : act0;
                if (c < 3) {
                    float* nxt = ((c + 1) & 1) ? act1 : act0;
                    load_rows64(nxt, g_zB + (mh * 64) * BBd + (c + 1) * 64, BBd);
                    cp_commit();
                    cp_wait1();
                } else {
                    cp_wait0();
                }
                __syncthreads();
                mac_heads(cur, smf + OFF_WH + c * 64, mg, n, acc);
                __syncthreads();
            }
            int j = jh * 16 + n;
#pragma unroll
            for (int i = 0; i < 4; i++) {
                int b = mh * 64 + mg * 4 + i;
                float tst = ts[(size_t)b * Ss + t];
                float f1  = tanhf(sum2(acc[i][0]) + bf1);
                float f2  = tanhf(sum2(acc[i][1]) + bf2);
                float ta_ = sum2(acc[i][2]) + bta;
                float tb_ = sum2(acc[i][3]) + btb;
                float ti  = 1.0f / (1.0f + expf(-(ta_ * tst + tb_)));
                g_h[b * Hh + j] = f1 + ti * (f2 - f1);
            }
        }
        group_barrier(barH, 32);
    }

    // ================= final: out = h_last @ W_out + b_out ================
    // CTA g reads h rows 8*(g>>2)..+8, which lie inside its mh group's rows
    // (synced by the final barH above).
    {
        int mo = g >> 2, no = g & 3;
        int m  = mo * 8 + (tid >> 5);
        int nn = no * 32 + (tid & 31);
        float acc = b_out[nn];
        const float* hr = g_h + m * Hh;
#pragma unroll 8
        for (int k = 0; k < Hh; k++) acc += hr[k] * W_out[k * Oo + nn];
        out[m * Oo + nn] = acc;
    }
}

extern "C" void kernel_launch(void* const* d_in, const int* in_sizes, int n_in,
                              void* d_out, int out_size) {
    const float* x     = (const float*)d_in[0];
    const float* ts    = (const float*)d_in[1];
    const float* Wb0   = (const float*)d_in[2];
    const float* bb0   = (const float*)d_in[3];
    const float* Wbs   = (const float*)d_in[4];
    const float* bbs   = (const float*)d_in[5];
    const float* W_ff1 = (const float*)d_in[6];
    const float* b_ff1 = (const float*)d_in[7];
    const float* W_ff2 = (const float*)d_in[8];
    const float* b_ff2 = (const float*)d_in[9];
    const float* W_ta  = (const float*)d_in[10];
    const float* b_ta  = (const float*)d_in[11];
    const float* W_tb  = (const float*)d_in[12];
    const float* b_tb  = (const float*)d_in[13];
    const float* W_out = (const float*)d_in[14];
    const float* b_out = (const float*)d_in[15];

    cudaFuncSetAttribute(lnn_kernel, cudaFuncAttributeMaxDynamicSharedMemorySize, SMEM_BYTES);
    lnn_kernel<<<NCTA, NTHR, SMEM_BYTES>>>(x, ts, Wb0, bb0, Wbs, bbs,
                                           W_ff1, b_ff1, W_ff2, b_ff2,
                                           W_ta, b_ta, W_tb, b_tb,
                                           W_out, b_out, (float*)d_out);
}